// round 2
// baseline (speedup 1.0000x reference)
#include <cuda_runtime.h>

// QueryEncDec: 2x128-layer scalar GRU (H=in=1), T=256, fused as one 256-layer
// wavefront. Thread = global layer; layer->layer handoff is an intra-warp
// shuffle; the 7 warp boundaries use write-once 64-bit smem mailboxes with a
// spin-poll. NO per-step block barrier.
//
// out[0:256]   = dec_out  (layer 255 output at each t)
// out[256:384] = dec_h    (final hidden of global layers 128..255)

#define GRU_T  256
#define NW     8
#define WSTEPS (GRU_T + 31)   // 287 steps per warp

__device__ __forceinline__ float frcp(float a) {
    float r; asm("rcp.approx.f32 %0, %1;" : "=f"(r) : "f"(a)); return r;
}
__device__ __forceinline__ float fex2(float a) {
    float r; asm("ex2.approx.f32 %0, %1;" : "=f"(r) : "f"(a)); return r;
}

__global__ __launch_bounds__(256, 1)
void gru_wave_shfl(const float* __restrict__ X,
                   const float* __restrict__ ewi, const float* __restrict__ ewh,
                   const float* __restrict__ ebi, const float* __restrict__ ebh,
                   const float* __restrict__ dwi, const float* __restrict__ dwh,
                   const float* __restrict__ dbi, const float* __restrict__ dbh,
                   float* __restrict__ out)
{
    const int tid  = threadIdx.x;
    const int l    = tid;          // global layer 0..255
    const int w    = tid >> 5;
    const int lane = tid & 31;

    __shared__ float xs[GRU_T];
    // boundary b: written once per diagonal by warp b lane31, read by warp b+1 lane0
    __shared__ volatile unsigned long long mb[NW - 1][512];

    // init mailboxes (write-once slots, hi word 0 = empty)
    for (int i = tid; i < (NW - 1) * 512; i += 256)
        ((volatile unsigned long long*)&mb[0][0])[i] = 0ULL;
    if (w == 0)
        for (int i = lane; i < GRU_T; i += 32) xs[i] = X[i];

    // per-layer scalar weights (torch gate order r,z,n)
    const bool  enc = (l < 128);
    const int   li  = enc ? l : (l - 128);
    const float* wi = enc ? ewi : dwi;
    const float* wh = enc ? ewh : dwh;
    const float* bi = enc ? ebi : dbi;
    const float* bh = enc ? ebh : dbh;

    const float wi_r = wi[li*3+0], wi_z = wi[li*3+1], wi_n = wi[li*3+2];
    const float wh_r = wh[li*3+0], wh_z = wh[li*3+1], wh_n = wh[li*3+2];
    const float bi_r = bi[li*3+0], bi_z = bi[li*3+1], bi_n = bi[li*3+2];
    const float bh_r = bh[li*3+0], bh_z = bh[li*3+1], bh_n = bh[li*3+2];

    const float L2E = 1.4426950408889634f;   // log2(e)
    const float K   = -2.0f * L2E;

    // sigmoid(u) = rcp(1 + ex2(-u*log2e)): pre-negate & pre-scale weights
    const float nwi_r = -wi_r * L2E,  nwi_z = -wi_z * L2E;
    const float Lwh_r = -wh_r * L2E,  Lwh_z = -wh_z * L2E;
    const float Lsb_r = -(bi_r + bh_r) * L2E;
    const float Lsb_z = -(bi_z + bh_z) * L2E;
    // tanh(a) = (1-e)/(1+e), e = ex2(-2*log2e*a): prefold K into n-gate weights
    const float kwi_n = K * wi_n, kbi_n = K * bi_n;
    const float kwh_n = K * wh_n, kbh_n = K * bh_n;

    float h = 0.0f;
    // h-dependent terms for the first step (h = 0), kept off the x-chain
    float nc_r = Lsb_r;          // fma(Lwh_r, h, Lsb_r)
    float nc_z = Lsb_z;
    float gh2  = kbh_n;          // K*(wh_n*h + bh_n)

    __syncthreads();             // mailboxes + xs visible

    const int d0 = w * 32;
    volatile const unsigned long long* inbox  = (w > 0)      ? &mb[w-1][0] : 0;
    volatile unsigned long long*       outbox = (w < NW - 1) ? &mb[w][0]   : 0;
    const bool is_tail   = (lane == 31) && (w < NW - 1);
    const bool is_head   = (lane == 0);

    #pragma unroll 1
    for (int s = 0; s < WSTEPS; ++s) {
        const int d = d0 + s;
        const int t = d - l;
        const bool valid = (t >= 0) && (t < GRU_T);

        // layer-(l-1) output at time t, produced last step by lane l-1
        float x = __shfl_up_sync(0xFFFFFFFFu, h, 1);
        if (is_head && valid) {
            if (w == 0) {
                x = xs[t];
            } else {
                unsigned long long v;
                do { v = inbox[d - 1]; } while ((unsigned)(v >> 32) == 0u);
                x = __uint_as_float((unsigned)v);
            }
        }

        if (valid) {
            // r, z gates (two independent MUFU chains)
            const float er = fex2(fmaf(nwi_r, x, nc_r));
            const float r  = frcp(1.0f + er);
            const float ez = fex2(fmaf(nwi_z, x, nc_z));
            const float z  = frcp(1.0f + ez);
            // n = tanh(wi_n*x + bi_n + r*(wh_n*h + bh_n))
            const float e2  = fex2(fmaf(r, gh2, fmaf(kwi_n, x, kbi_n)));
            const float n   = (1.0f - e2) * frcp(1.0f + e2);
            // h' = z*(h-n) + n
            h = fmaf(z, h - n, n);

            if (is_tail)
                outbox[d] = ((unsigned long long)(unsigned)(d + 1) << 32)
                          | (unsigned long long)__float_as_uint(h);

            // next step's h-dependent terms (off the next x-chain)
            nc_r = fmaf(Lwh_r, h, Lsb_r);
            nc_z = fmaf(Lwh_z, h, Lsb_z);
            gh2  = fmaf(kwh_n, h, kbh_n);

            if (l == 255)                 out[t] = h;                   // dec_out
            if (t == GRU_T - 1 && l >= 128) out[GRU_T + (l - 128)] = h; // dec_h
        }
    }
}

extern "C" void kernel_launch(void* const* d_in, const int* in_sizes, int n_in,
                              void* d_out, int out_size)
{
    const float* X   = (const float*)d_in[0];
    const float* ewi = (const float*)d_in[1];
    const float* ewh = (const float*)d_in[2];
    const float* ebi = (const float*)d_in[3];
    const float* ebh = (const float*)d_in[4];
    const float* dwi = (const float*)d_in[5];
    const float* dwh = (const float*)d_in[6];
    const float* dbi = (const float*)d_in[7];
    const float* dbh = (const float*)d_in[8];
    float* out = (float*)d_out;

    gru_wave_shfl<<<1, 256>>>(X, ewi, ewh, ebi, ebh, dwi, dwh, dbi, dbh, out);
}